// round 2
// baseline (speedup 1.0000x reference)
#include <cuda_runtime.h>
#include <math.h>

// Problem constants (fixed-shape problem; verified against in_sizes at launch)
#define N_CELLS 1024
#define L_DIM   30
#define G_GENES 10000
#define NB_BATCH 64

#define TG   128   // genes per block == threads per block
#define CMAX 64    // max cells per shared-memory chunk

// Scratch (no device allocs allowed) — cell permutation grouped by batch
__device__ int d_batch_start[NB_BATCH + 1];
__device__ int d_cell_perm[N_CELLS];

// ---------------------------------------------------------------------------
// Kernel 1: counting sort of cells by batch covariate. One block, N threads.
// ---------------------------------------------------------------------------
__global__ void sort_cells_kernel(const int* __restrict__ batch, int n) {
    __shared__ int cnt[NB_BATCH];
    __shared__ int off[NB_BATCH + 1];
    __shared__ int cur[NB_BATCH];
    int tid = threadIdx.x;
    if (tid < NB_BATCH) cnt[tid] = 0;
    __syncthreads();
    if (tid < n) atomicAdd(&cnt[batch[tid]], 1);
    __syncthreads();
    if (tid == 0) {
        int s = 0;
        for (int b = 0; b < NB_BATCH; b++) { off[b] = s; s += cnt[b]; }
        off[NB_BATCH] = s;
    }
    __syncthreads();
    if (tid <= NB_BATCH) d_batch_start[tid] = off[tid];
    if (tid < NB_BATCH) cur[tid] = off[tid];
    __syncthreads();
    if (tid < n) {
        int pos = atomicAdd(&cur[batch[tid]], 1);
        d_cell_perm[pos] = tid;
    }
}

// ---------------------------------------------------------------------------
// Kernel 2: main decoder.
// grid = (ceil(G/TG), NB). Each thread owns one gene g for batch b:
//   coef[l] = W[l,g] + A[b,g,l]   (read ONCE, reused for all cells of batch b)
//   for each cell c in batch b:
//     mean[c,g] = softplus(dot(coef, z[c]) + b_emb[b,g]) * size_factor[c]
// ---------------------------------------------------------------------------
__global__ __launch_bounds__(TG) void decoder_kernel(
    const float* __restrict__ z,      // [N, L]
    const float* __restrict__ sf,     // [N, 1]
    const float* __restrict__ W,      // [L, G]
    const float* __restrict__ A,      // [NB, G, L]
    const float* __restrict__ Bemb,   // [NB, G]
    float* __restrict__ out)          // [N, G]
{
    const int b = blockIdx.y;
    const int g = blockIdx.x * TG + threadIdx.x;
    const int start = d_batch_start[b];
    const int m = d_batch_start[b + 1] - start;

    __shared__ float zs[CMAX][L_DIM];
    __shared__ float sfs[CMAX];
    __shared__ int   cidx[CMAX];

    float coef[L_DIM];
    float bg = 0.f;
    if (g < G_GENES) {
        const float* a = A + ((size_t)b * G_GENES + (size_t)g) * L_DIM;
        #pragma unroll
        for (int l = 0; l < L_DIM; l++)
            coef[l] = W[(size_t)l * G_GENES + g] + a[l];
        bg = Bemb[(size_t)b * G_GENES + g];
    }

    for (int c0 = 0; c0 < m; c0 += CMAX) {
        const int mc = min(CMAX, m - c0);
        __syncthreads();   // protect smem from previous chunk's readers
        // stage z rows + size factors + cell indices for this chunk
        for (int i = threadIdx.x; i < mc * L_DIM; i += TG) {
            int c = i / L_DIM;
            int l = i - c * L_DIM;
            int cell = d_cell_perm[start + c0 + c];
            zs[c][l] = z[cell * L_DIM + l];
        }
        for (int i = threadIdx.x; i < mc; i += TG) {
            int cell = d_cell_perm[start + c0 + i];
            cidx[i] = cell;
            sfs[i]  = sf[cell];
        }
        __syncthreads();

        if (g < G_GENES) {
            for (int c = 0; c < mc; c++) {
                float acc = bg;
                #pragma unroll
                for (int l = 0; l < L_DIM; l++)
                    acc = fmaf(coef[l], zs[c][l], acc);
                // numerically-stable softplus, matches jax.nn.softplus
                float sp = fmaxf(acc, 0.f) + log1pf(expf(-fabsf(acc)));
                out[(size_t)cidx[c] * G_GENES + g] = sp * sfs[c];
            }
        }
    }
}

// ---------------------------------------------------------------------------
// Kernel 3: inverse_dispersion = exp(px_r)  -> second output region
// ---------------------------------------------------------------------------
__global__ void expr_kernel(const float* __restrict__ px_r,
                            float* __restrict__ out_id) {
    int g = blockIdx.x * 256 + threadIdx.x;
    if (g < G_GENES) out_id[g] = expf(px_r[g]);
}

// ---------------------------------------------------------------------------
extern "C" void kernel_launch(void* const* d_in, const int* in_sizes, int n_in,
                              void* d_out, int out_size) {
    const float* z     = (const float*)d_in[0];   // [N, L]
    const int*   batch = (const int*)  d_in[1];   // [N]
    const float* sf    = (const float*)d_in[2];   // [N, 1]
    const float* W     = (const float*)d_in[3];   // [L, G]
    const float* A     = (const float*)d_in[4];   // [NB, G, L]
    const float* Bemb  = (const float*)d_in[5];   // [NB, G]
    const float* pxr   = (const float*)d_in[6];   // [G]
    float* out = (float*)d_out;                   // [N*G mean] ++ [G inv_disp]

    sort_cells_kernel<<<1, N_CELLS>>>(batch, N_CELLS);

    dim3 grid((G_GENES + TG - 1) / TG, NB_BATCH);
    decoder_kernel<<<grid, TG>>>(z, sf, W, A, Bemb, out);

    expr_kernel<<<(G_GENES + 255) / 256, 256>>>(
        pxr, out + (size_t)N_CELLS * G_GENES);
}

// round 4
// speedup vs baseline: 1.0731x; 1.0731x over previous
#include <cuda_runtime.h>
#include <math.h>

#define N_CELLS  1024
#define L_DIM    30
#define G_GENES  10000
#define NB_BATCH 64
#define TG       128            // genes per block == threads
#define CMAX     64             // cells per smem chunk (must be even)

typedef unsigned long long ull;

__device__ __forceinline__ ull pack2(float lo, float hi) {
    ull r;
    asm("mov.b64 %0, {%1, %2};" : "=l"(r)
        : "r"(__float_as_uint(lo)), "r"(__float_as_uint(hi)));
    return r;
}
__device__ __forceinline__ void unpack2(ull v, float& lo, float& hi) {
    unsigned u0, u1;
    asm("mov.b64 {%0, %1}, %2;" : "=r"(u0), "=r"(u1) : "l"(v));
    lo = __uint_as_float(u0);
    hi = __uint_as_float(u1);
}
// packed dual-fp32 FMA (sm_10x): d = a*b + c on both lanes
__device__ __forceinline__ ull fma2(ull a, ull b, ull c) {
    ull d;
    asm("fma.rn.f32x2 %0, %1, %2, %3;" : "=l"(d) : "l"(a), "l"(b), "l"(c));
    return d;
}

__device__ __forceinline__ float softplus_fast(float x) {
    // max(x,0) + log1p(exp(-|x|)); fast intrinsics (margin vs 1e-3 is huge)
    return fmaxf(x, 0.f) + __logf(1.f + __expf(-fabsf(x)));
}

// ---------------------------------------------------------------------------
// Single fused kernel. grid = (ceil(G/TG), NB).
// Each block: batch b, genes [g0, g0+TG).
//   1. (b==0 blocks) write inverse_dispersion = exp(px_r)
//   2. scan batch[] (4KB, L2-resident) -> compact this batch's cell list
//   3. coalesced-stage A[b, g0:g0+TG, :] into smem (float4), fuse
//      coef = W + A into duplicated f32x2 register pairs
//   4. per 2-cell pair: 30x { LDS.64 z-pair ; FFMA2 } -> softplus -> store
// ---------------------------------------------------------------------------
__global__ __launch_bounds__(TG) void decoder_fused(
    const float* __restrict__ z,      // [N, L]
    const int*   __restrict__ batch,  // [N]
    const float* __restrict__ sf,     // [N, 1]
    const float* __restrict__ W,      // [L, G]
    const float* __restrict__ A,      // [NB, G, L]
    const float* __restrict__ Bemb,   // [NB, G]
    const float* __restrict__ px_r,   // [G]
    float* __restrict__ out)          // [N*G mean] ++ [G inv_disp]
{
    const int b   = blockIdx.y;
    const int g0  = blockIdx.x * TG;
    const int tid = threadIdx.x;
    const int g   = g0 + tid;
    const int gv  = min(TG, G_GENES - g0);        // valid genes in this block

    __shared__ __align__(16) float s_A[TG * L_DIM];   // A chunk [g_local*30 + l]
    __shared__ __align__(8)  float s_zs[L_DIM][CMAX + 2]; // z as [l][cell]
    __shared__ int   s_cidx[N_CELLS];
    __shared__ float s_sf[CMAX];
    __shared__ int   s_cnt;

    // ---- inverse dispersion (only one row of blocks) ----
    if (b == 0 && g < G_GENES)
        out[(size_t)N_CELLS * G_GENES + g] = expf(px_r[g]);

    // ---- build this batch's cell list (order-independent results) ----
    if (tid == 0) s_cnt = 0;
    __syncthreads();
    for (int i = tid; i < N_CELLS; i += TG)
        if (batch[i] == b) {
            int p = atomicAdd(&s_cnt, 1);
            s_cidx[p] = i;
        }

    // ---- coalesced stage of A chunk (float4) ----
    {
        const float4* Ab = reinterpret_cast<const float4*>(
            A + ((size_t)b * G_GENES + g0) * L_DIM);
        const int nf4 = (gv * L_DIM) >> 2;        // float4 count
        float4* s_A4 = reinterpret_cast<float4*>(s_A);
        for (int i = tid; i < nf4; i += TG) s_A4[i] = Ab[i];
    }
    __syncthreads();
    const int m = s_cnt;

    // ---- fused coefficients: coefd[l] = {W[l,g]+A[b,g,l]} duplicated ----
    ull coefd[L_DIM];
    ull bgd = 0;
    if (g < G_GENES) {
        #pragma unroll
        for (int l = 0; l < L_DIM; l++) {
            float c = W[(size_t)l * G_GENES + g] + s_A[tid * L_DIM + l];
            coefd[l] = pack2(c, c);
        }
        float bgv = Bemb[(size_t)b * G_GENES + g];
        bgd = pack2(bgv, bgv);
    }

    // ---- main loop over this batch's cells, in smem chunks ----
    for (int c0 = 0; c0 < m; c0 += CMAX) {
        const int mc = min(CMAX, m - c0);
        __syncthreads();                          // protect smem reuse
        for (int i = tid; i < mc * L_DIM; i += TG) {
            int c = i / L_DIM;
            int l = i - c * L_DIM;
            s_zs[l][c] = z[s_cidx[c0 + c] * L_DIM + l];
        }
        if (mc & 1)                               // zero-pad odd tail column
            for (int l = tid; l < L_DIM; l += TG) s_zs[l][mc] = 0.f;
        if (tid < mc) s_sf[tid] = sf[s_cidx[c0 + tid]];
        __syncthreads();

        if (g < G_GENES) {
            for (int c = 0; c < mc; c += 2) {
                ull acc = bgd;
                #pragma unroll
                for (int l = 0; l < L_DIM; l++) {
                    // adjacent cells -> single 8B broadcast LDS
                    ull zz = *reinterpret_cast<const ull*>(&s_zs[l][c]);
                    acc = fma2(coefd[l], zz, acc);
                }
                float a0, a1;
                unpack2(acc, a0, a1);
                out[(size_t)s_cidx[c0 + c] * G_GENES + g] =
                    softplus_fast(a0) * s_sf[c];
                if (c + 1 < mc)
                    out[(size_t)s_cidx[c0 + c + 1] * G_GENES + g] =
                        softplus_fast(a1) * s_sf[c + 1];
            }
        }
    }
}

// ---------------------------------------------------------------------------
extern "C" void kernel_launch(void* const* d_in, const int* in_sizes, int n_in,
                              void* d_out, int out_size) {
    const float* z     = (const float*)d_in[0];   // [N, L]
    const int*   batch = (const int*)  d_in[1];   // [N]
    const float* sf    = (const float*)d_in[2];   // [N, 1]
    const float* W     = (const float*)d_in[3];   // [L, G]
    const float* A     = (const float*)d_in[4];   // [NB, G, L]
    const float* Bemb  = (const float*)d_in[5];   // [NB, G]
    const float* pxr   = (const float*)d_in[6];   // [G]
    float* out = (float*)d_out;

    dim3 grid((G_GENES + TG - 1) / TG, NB_BATCH);
    decoder_fused<<<grid, TG>>>(z, batch, sf, W, A, Bemb, pxr, out);
}

// round 5
// speedup vs baseline: 1.1728x; 1.0930x over previous
#include <cuda_runtime.h>
#include <math.h>

#define N_CELLS  1024
#define L_DIM    30
#define G_GENES  10000
#define NB_BATCH 64
#define TG       128            // genes per block == threads
#define CMAX     112            // cells per smem chunk (even; 112*128B <= union buf)

typedef unsigned long long ull;

__device__ __forceinline__ ull pack2(float lo, float hi) {
    ull r;
    asm("mov.b64 %0, {%1, %2};" : "=l"(r)
        : "r"(__float_as_uint(lo)), "r"(__float_as_uint(hi)));
    return r;
}
__device__ __forceinline__ void unpack2(ull v, float& lo, float& hi) {
    unsigned u0, u1;
    asm("mov.b64 {%0, %1}, %2;" : "=r"(u0), "=r"(u1) : "l"(v));
    lo = __uint_as_float(u0);
    hi = __uint_as_float(u1);
}
// packed dual-fp32 FMA (sm_10x): d = a*b + c on both lanes
__device__ __forceinline__ ull fma2(ull a, ull b, ull c) {
    ull d;
    asm("fma.rn.f32x2 %0, %1, %2, %3;" : "=l"(d) : "l"(a), "l"(b), "l"(c));
    return d;
}

__device__ __forceinline__ float softplus_fast(float x) {
    return fmaxf(x, 0.f) + __logf(1.f + __expf(-fabsf(x)));
}

// ---------------------------------------------------------------------------
// Single fused kernel. grid = (ceil(G/TG), NB). Block: batch b, genes [g0,g0+TG).
// Inner loop vectorized over L: z staged as [cell][32] (128B rows), coefs
// packed as 15 natural (c[2j],c[2j+1]) f32x2 pairs + 1 zero pad.
// Per cell: 8 LDS.128 + 16 FFMA2. smem union keeps footprint ~18KB.
// ---------------------------------------------------------------------------
__global__ __launch_bounds__(TG) void decoder_fused(
    const float* __restrict__ z,      // [N, L]
    const int*   __restrict__ batch,  // [N]
    const float* __restrict__ sf,     // [N, 1]
    const float* __restrict__ W,      // [L, G]
    const float* __restrict__ A,      // [NB, G, L]
    const float* __restrict__ Bemb,   // [NB, G]
    const float* __restrict__ px_r,   // [G]
    float* __restrict__ out)          // [N*G mean] ++ [G inv_disp]
{
    const int b   = blockIdx.y;
    const int g0  = blockIdx.x * TG;
    const int tid = threadIdx.x;
    const int g   = g0 + tid;

    // 15360B union: A chunk (TG*30 floats) OR z tile (CMAX rows x 32 floats)
    __shared__ __align__(16) float s_buf[TG * L_DIM];
    __shared__ unsigned short s_cidx[N_CELLS];
    __shared__ float s_sf[CMAX];
    __shared__ int   s_cnt;

    float* s_A = s_buf;
    float (*s_z)[32] = reinterpret_cast<float(*)[32]>(s_buf);

    // ---- inverse dispersion (one row of blocks) ----
    if (b == 0 && g < G_GENES)
        out[(size_t)N_CELLS * G_GENES + g] = expf(px_r[g]);

    // ---- build this batch's cell list (4KB batch[] scan, L2-resident) ----
    if (tid == 0) s_cnt = 0;
    __syncthreads();
    for (int i = tid; i < N_CELLS; i += TG)
        if (batch[i] == b)
            s_cidx[atomicAdd(&s_cnt, 1)] = (unsigned short)i;

    // ---- coalesced stage of A chunk (float4) ----
    {
        const int gv = min(TG, G_GENES - g0);
        const float4* Ab = reinterpret_cast<const float4*>(
            A + ((size_t)b * G_GENES + g0) * L_DIM);
        float4* s4 = reinterpret_cast<float4*>(s_A);
        const int nf4 = (gv * L_DIM) >> 2;
        for (int i = tid; i < nf4; i += TG) s4[i] = Ab[i];
    }
    __syncthreads();
    const int m = s_cnt;

    // ---- fused coefficients as 15 natural f32x2 pairs (+1 zero pad) ----
    ull coefp[16];
    ull accInit = 0;
    if (g < G_GENES) {
        float c[L_DIM];
        #pragma unroll
        for (int l = 0; l < L_DIM; l++)
            c[l] = W[(size_t)l * G_GENES + g] + s_A[tid * L_DIM + l];
        #pragma unroll
        for (int j = 0; j < 15; j++)
            coefp[j] = pack2(c[2 * j], c[2 * j + 1]);
        coefp[15] = 0;  // pad pair (l=30,31) -> 0 * z_pad(=0)
        accInit = pack2(Bemb[(size_t)b * G_GENES + g], 0.f);
    } else {
        #pragma unroll
        for (int j = 0; j < 16; j++) coefp[j] = 0;
    }

    // ---- main loop over this batch's cells (usually one chunk) ----
    for (int c0 = 0; c0 < m; c0 += CMAX) {
        const int mc  = min(CMAX, m - c0);
        const int mcp = (mc + 1) & ~1;            // pad to even rows
        __syncthreads();                          // union / chunk reuse
        for (int i = tid; i < mcp * 32; i += TG) {
            int c = i >> 5, l = i & 31;
            float v = 0.f;
            if (l < L_DIM && c < mc)
                v = z[(int)s_cidx[c0 + c] * L_DIM + l];
            s_z[c][l] = v;                        // pads (l>=30, c==mc) -> 0
        }
        if (tid < mc) s_sf[tid] = sf[s_cidx[c0 + tid]];
        __syncthreads();

        if (g < G_GENES) {
            for (int c = 0; c < mc; c += 2) {
                const ulonglong2* r0 =
                    reinterpret_cast<const ulonglong2*>(s_z[c]);
                const ulonglong2* r1 =
                    reinterpret_cast<const ulonglong2*>(s_z[c + 1]);
                ull a0 = accInit, a1 = accInit;
                #pragma unroll
                for (int j = 0; j < 8; j++) {
                    ulonglong2 v0 = r0[j];        // LDS.128 broadcast
                    ulonglong2 v1 = r1[j];
                    a0 = fma2(coefp[2 * j],     v0.x, a0);
                    a0 = fma2(coefp[2 * j + 1], v0.y, a0);
                    a1 = fma2(coefp[2 * j],     v1.x, a1);
                    a1 = fma2(coefp[2 * j + 1], v1.y, a1);
                }
                float e0, o0, e1, o1;
                unpack2(a0, e0, o0);
                unpack2(a1, e1, o1);
                float x0 = e0 + o0, x1 = e1 + o1;
                out[(size_t)s_cidx[c0 + c] * G_GENES + g] =
                    softplus_fast(x0) * s_sf[c];
                if (c + 1 < mc)
                    out[(size_t)s_cidx[c0 + c + 1] * G_GENES + g] =
                        softplus_fast(x1) * s_sf[c + 1];
            }
        }
    }
}

// ---------------------------------------------------------------------------
extern "C" void kernel_launch(void* const* d_in, const int* in_sizes, int n_in,
                              void* d_out, int out_size) {
    const float* z     = (const float*)d_in[0];   // [N, L]
    const int*   batch = (const int*)  d_in[1];   // [N]
    const float* sf    = (const float*)d_in[2];   // [N, 1]
    const float* W     = (const float*)d_in[3];   // [L, G]
    const float* A     = (const float*)d_in[4];   // [NB, G, L]
    const float* Bemb  = (const float*)d_in[5];   // [NB, G]
    const float* pxr   = (const float*)d_in[6];   // [G]
    float* out = (float*)d_out;

    dim3 grid((G_GENES + TG - 1) / TG, NB_BATCH);
    decoder_fused<<<grid, TG>>>(z, batch, sf, W, A, Bemb, pxr, out);
}